// round 15
// baseline (speedup 1.0000x reference)
#include <cuda_runtime.h>
#include <cuda_fp16.h>
#include <cstdint>

#define C 64
#define KSZ 27
#define TM 64
#define NMAX 100000
#define EPSV 1e-5f

// 3 stages, each: A 8KB + W 8KB = 16KB -> 48KB dyn; 4 CTAs/SM target
#define STAGE_BYTES 16384
#define SMEM_DYN (3 * STAGE_BYTES + 1024)

// Device scratch (no allocation allowed)
__device__ float g_y1[NMAX * C];
__device__ float g_sum1[C], g_sq1[C], g_sum2[C], g_sq2[C];
// fp16 activations, row-major [n][64] (128B rows)
__device__ __align__(16) __half g_a[NMAX * C];
// weights [conv][k][d][c] fp16, PRE-SWIZZLED for linear smem copy
__device__ __align__(16) __half g_wt[2 * KSZ * C * C];

// ---------------- helpers ----------------
static __device__ __forceinline__ uint32_t smem_u32(const void* p) {
    uint32_t a;
    asm("{ .reg .u64 t; cvta.to.shared.u64 t, %1; cvt.u32.u64 %0, t; }" : "=r"(a) : "l"(p));
    return a;
}
static __device__ __forceinline__ void cp_async16(uint32_t dst, const void* src) {
    asm volatile("cp.async.cg.shared.global [%0], [%1], 16;"
                 :: "r"(dst), "l"(__cvta_generic_to_global(src)) : "memory");
}
static __device__ __forceinline__ void cp_commit() {
    asm volatile("cp.async.commit_group;" ::: "memory");
}
static __device__ __forceinline__ void cp_wait1() {
    asm volatile("cp.async.wait_group 1;" ::: "memory");
}
static __device__ __forceinline__ void ldm4(uint32_t* r, uint32_t addr) {
    asm volatile("ldmatrix.sync.aligned.m8n8.x4.shared.b16 {%0,%1,%2,%3}, [%4];"
                 : "=r"(r[0]), "=r"(r[1]), "=r"(r[2]), "=r"(r[3]) : "r"(addr));
}
static __device__ __forceinline__ void mma_f16(float* c, const uint32_t* a, const uint32_t* b) {
    asm("mma.sync.aligned.m16n8k16.row.col.f32.f16.f16.f32 "
        "{%0,%1,%2,%3}, {%4,%5,%6,%7}, {%8,%9}, {%0,%1,%2,%3};"
        : "+f"(c[0]), "+f"(c[1]), "+f"(c[2]), "+f"(c[3])
        : "r"(a[0]), "r"(a[1]), "r"(a[2]), "r"(a[3]), "r"(b[0]), "r"(b[1]));
}

// ---------------- fused prep: zero stats + W prep + feats->fp16 ----------------
__global__ void prep_all_kernel(const float* __restrict__ W1, const float* __restrict__ W2,
                                const float* __restrict__ feats, int n) {
    int b = blockIdx.x, tid = threadIdx.x;
    if (b == 0 && tid < C) {
        g_sum1[tid] = 0.f; g_sq1[tid] = 0.f; g_sum2[tid] = 0.f; g_sq2[tid] = 0.f;
    }
    if (b < 2 * KSZ) {
        int conv = b / KSZ, k = b % KSZ;
        __half* dst = g_wt + (size_t)b * C * C;
        const float* W = ((conv == 0) ? W1 : W2) + (size_t)k * C * C;
        #pragma unroll
        for (int i = 0; i < 16; ++i) {
            int e = tid + i * 256;     // 0..4095
            int c = e >> 6, d = e & 63;
            float v = W[c * C + d];
            uint32_t sseg = (uint32_t)((c >> 3) ^ (d & 7));
            dst[(uint32_t)d * 64u + sseg * 8u + (uint32_t)(c & 7)] = __float2half_rn(v);
        }
        return;
    }
    int i = (b - 2 * KSZ) * 256 + tid;        // float4 index
    int total = n * (C / 4);
    if (i >= total) return;
    float4 v = ((const float4*)feats)[i];
    __half2 a = __floats2half2_rn(v.x, v.y);
    __half2 bb = __floats2half2_rn(v.z, v.w);
    ((uint2*)g_a)[i] = make_uint2(*(uint32_t*)&a, *(uint32_t*)&bb);
}

// y1 -> BN1(inline stats)+ReLU -> fp16 (overwrites g_a)
__global__ void prep_h1_kernel(const float* __restrict__ gamma,
                               const float* __restrict__ beta, int n) {
    __shared__ float s_sc[C], s_sh[C];
    int tid = threadIdx.x;
    if (tid < C) {
        float inv_n = 1.0f / (float)n;
        float mean = g_sum1[tid] * inv_n;
        float var = fmaxf(g_sq1[tid] * inv_n - mean * mean, 0.f);
        float sc = gamma[tid] * rsqrtf(var + EPSV);
        s_sc[tid] = sc;
        s_sh[tid] = beta[tid] - mean * sc;
    }
    __syncthreads();
    int i = blockIdx.x * blockDim.x + tid;
    int total = n * (C / 4);
    if (i >= total) return;
    int c = (i & 15) * 4;
    float4 v = ((const float4*)g_y1)[i];
    v.x = fmaxf(fmaf(v.x, s_sc[c + 0], s_sh[c + 0]), 0.f);
    v.y = fmaxf(fmaf(v.y, s_sc[c + 1], s_sh[c + 1]), 0.f);
    v.z = fmaxf(fmaf(v.z, s_sc[c + 2], s_sh[c + 2]), 0.f);
    v.w = fmaxf(fmaf(v.w, s_sc[c + 3], s_sh[c + 3]), 0.f);
    __half2 a = __floats2half2_rn(v.x, v.y);
    __half2 b = __floats2half2_rn(v.z, v.w);
    ((uint2*)g_a)[i] = make_uint2(*(uint32_t*)&a, *(uint32_t*)&b);
}

// out = relu(bn2(y2)+feats), stats2 inlined
__global__ void final_kernel(const float* __restrict__ feats,
                             const float* __restrict__ gamma,
                             const float* __restrict__ beta,
                             float* __restrict__ out, int n) {
    __shared__ float s_sc[C], s_sh[C];
    int tid = threadIdx.x;
    if (tid < C) {
        float inv_n = 1.0f / (float)n;
        float mean = g_sum2[tid] * inv_n;
        float var = fmaxf(g_sq2[tid] * inv_n - mean * mean, 0.f);
        float sc = gamma[tid] * rsqrtf(var + EPSV);
        s_sc[tid] = sc;
        s_sh[tid] = beta[tid] - mean * sc;
    }
    __syncthreads();
    int i = blockIdx.x * blockDim.x + tid;
    int total = n * (C / 4);
    if (i >= total) return;
    int c = (i & 15) * 4;
    float4 y = ((const float4*)out)[i];
    float4 f = ((const float4*)feats)[i];
    float4 r;
    r.x = fmaxf(fmaf(y.x, s_sc[c + 0], s_sh[c + 0]) + f.x, 0.f);
    r.y = fmaxf(fmaf(y.y, s_sc[c + 1], s_sh[c + 1]) + f.y, 0.f);
    r.z = fmaxf(fmaf(y.z, s_sc[c + 2], s_sh[c + 2]) + f.z, 0.f);
    r.w = fmaxf(fmaf(y.w, s_sc[c + 3], s_sh[c + 3]) + f.w, 0.f);
    ((float4*)out)[i] = r;
}

// ---------------- main conv: TM=64, warp=16x32 tile, 3-stage ring, 4 CTAs/SM ----------------
template<int PASS>
__global__ __launch_bounds__(256, 4) void conv_mma_kernel(
    const int* __restrict__ nbr, const float* __restrict__ bias,
    float* __restrict__ dout, int n)
{
    extern __shared__ char dsm[];
    __shared__ float s_sum[C], s_sq[C], s_bias[C];

    float*       yout = (PASS == 0) ? g_y1   : dout;
    float*       gsum = (PASS == 0) ? g_sum1 : g_sum2;
    float*       gsq  = (PASS == 0) ? g_sq1  : g_sq2;

    const int tid = threadIdx.x, lane = tid & 31, w = tid >> 5;
    const uint32_t base = (smem_u32(dsm) + 1023u) & ~1023u;

    if (tid < C) { s_sum[tid] = 0.f; s_sq[tid] = 0.f; s_bias[tid] = bias[tid]; }

    // ---- copy-role: 8 segs (16B) per 128B row; 2 rows per thread ----
    const int cseg = tid & 7;
    const int crow = tid >> 3;                 // 0..31, rows crow, crow+32
    const long blk0 = (long)blockIdx.x * TM;

    const uint4* gw = (const uint4*)g_wt + (size_t)PASS * KSZ * 512;

    int pidx[2];
    auto load_idx = [&](int k) {
        #pragma unroll
        for (int i = 0; i < 2; ++i) {
            long r = blk0 + crow + 32 * i;
            pidx[i] = (r < (long)n) ? nbr[r * KSZ + k] : 0;
        }
    };
    auto issue_stage = [&](int k) {
        const uint32_t St = base + (uint32_t)(k % 3) * STAGE_BYTES;
        const uint32_t Wst = St + 8192u;
        #pragma unroll
        for (int i = 0; i < 2; ++i) {
            int r = crow + 32 * i;
            uint32_t dst = (uint32_t)r * 128u + (uint32_t)((cseg ^ (r & 7)) << 4);
            cp_async16(St + dst, g_a + (size_t)pidx[i] * 64 + cseg * 8);
        }
        #pragma unroll
        for (int i = 0; i < 2; ++i) {
            int jj = tid + i * 256;
            cp_async16(Wst + (uint32_t)jj * 16u, gw + (size_t)k * 512 + jj);
        }
        cp_commit();
    };

    // ---- mma-role: warp = (rowgrp, nhalf); 16 rows x 32 cols ----
    const int nhalf = w & 1, rowgrp = w >> 1;
    const int ar0 = rowgrp * 16 + (lane & 15);
    const int ahalf = lane >> 4;
    const int ax7 = lane & 7;
    const int bd = ((lane >> 4) & 1) * 8 + (lane & 7);
    const int bkh = (lane >> 3) & 1;
    const int bx7 = bd & 7;
    const uint32_t brow0 = (uint32_t)(nhalf * 32 + bd);

    float acc[4][4];
    #pragma unroll
    for (int nt = 0; nt < 4; ++nt)
        #pragma unroll
        for (int j = 0; j < 4; ++j) acc[nt][j] = 0.f;

    // ---- prologue: fill 2 stages ----
    load_idx(0); issue_stage(0);
    load_idx(1); issue_stage(1);
    load_idx(2);

    for (int k = 0; k < KSZ; ++k) {
        cp_wait1();
        __syncthreads();          // stage k ready; ring slot (k+2)%3 free

        if (k + 2 < KSZ) {
            issue_stage(k + 2);
            if (k + 3 < KSZ) load_idx(k + 3);
        }

        const uint32_t St = base + (uint32_t)(k % 3) * STAGE_BYTES;
        const uint32_t Wst = St + 8192u;

        #pragma unroll
        for (int kk = 0; kk < 4; ++kk) {
            uint32_t a0[4], b0[4], b1[4];
            uint32_t asel = (uint32_t)(((kk * 2 + ahalf) ^ ax7) << 4);
            uint32_t bsel = (uint32_t)(((kk * 2 + bkh) ^ bx7) << 4);
            ldm4(a0, St + (uint32_t)ar0 * 128u + asel);
            ldm4(b0, Wst + brow0 * 128u + bsel);
            ldm4(b1, Wst + (brow0 + 16u) * 128u + bsel);
            mma_f16(acc[0], a0, b0);
            mma_f16(acc[1], a0, b0 + 2);
            mma_f16(acc[2], a0, b1);
            mma_f16(acc[3], a0, b1 + 2);
        }
    }

    // ---------------- epilogue ----------------
    const int g = lane >> 2, tig = lane & 3;
    const long row0 = blk0 + rowgrp * 16 + g;
    const long row1 = row0 + 8;
    const bool v0 = row0 < (long)n, v1 = row1 < (long)n;

    #pragma unroll
    for (int nt = 0; nt < 4; ++nt) {
        int col = nhalf * 32 + nt * 8 + tig * 2;
        float b0 = s_bias[col], b1 = s_bias[col + 1];
        float y00 = v0 ? acc[nt][0] + b0 : 0.f;
        float y01 = v0 ? acc[nt][1] + b1 : 0.f;
        float y10 = v1 ? acc[nt][2] + b0 : 0.f;
        float y11 = v1 ? acc[nt][3] + b1 : 0.f;
        if (v0) *(float2*)(yout + (size_t)row0 * C + col) = make_float2(y00, y01);
        if (v1) *(float2*)(yout + (size_t)row1 * C + col) = make_float2(y10, y11);
        float sv0 = y00 + y10, sv1 = y01 + y11;
        float sq0 = y00 * y00 + y10 * y10, sq1 = y01 * y01 + y11 * y11;
        #pragma unroll
        for (int o = 16; o >= 4; o >>= 1) {
            sv0 += __shfl_xor_sync(0xffffffffu, sv0, o);
            sv1 += __shfl_xor_sync(0xffffffffu, sv1, o);
            sq0 += __shfl_xor_sync(0xffffffffu, sq0, o);
            sq1 += __shfl_xor_sync(0xffffffffu, sq1, o);
        }
        if (lane < 4) {
            atomicAdd(&s_sum[nhalf * 32 + nt * 8 + lane * 2],     sv0);
            atomicAdd(&s_sum[nhalf * 32 + nt * 8 + lane * 2 + 1], sv1);
            atomicAdd(&s_sq[nhalf * 32 + nt * 8 + lane * 2],      sq0);
            atomicAdd(&s_sq[nhalf * 32 + nt * 8 + lane * 2 + 1],  sq1);
        }
    }
    __syncthreads();
    if (tid < C) { atomicAdd(&gsum[tid], s_sum[tid]); atomicAdd(&gsq[tid], s_sq[tid]); }
}

extern "C" void kernel_launch(void* const* d_in, const int* in_sizes, int n_in,
                              void* d_out, int out_size) {
    const float* feats = (const float*)d_in[0];
    const int*   nbr   = (const int*)d_in[1];
    const float* W1    = (const float*)d_in[2];
    const float* b1    = (const float*)d_in[3];
    const float* g1    = (const float*)d_in[4];
    const float* be1   = (const float*)d_in[5];
    const float* W2    = (const float*)d_in[6];
    const float* b2    = (const float*)d_in[7];
    const float* g2    = (const float*)d_in[8];
    const float* be2   = (const float*)d_in[9];
    float* out = (float*)d_out;

    int n = in_sizes[0] / C;
    int conv_blocks = (n + TM - 1) / TM;
    int ew_blocks = (n * (C / 4) + 255) / 256;

    cudaFuncSetAttribute(conv_mma_kernel<0>, cudaFuncAttributeMaxDynamicSharedMemorySize, SMEM_DYN);
    cudaFuncSetAttribute(conv_mma_kernel<1>, cudaFuncAttributeMaxDynamicSharedMemorySize, SMEM_DYN);

    prep_all_kernel<<<2 * KSZ + ew_blocks, 256>>>(W1, W2, feats, n);
    conv_mma_kernel<0><<<conv_blocks, 256, SMEM_DYN>>>(nbr, b1, nullptr, n);
    prep_h1_kernel<<<ew_blocks, 256>>>(g1, be1, n);
    conv_mma_kernel<1><<<conv_blocks, 256, SMEM_DYN>>>(nbr, b2, out, n);
    final_kernel<<<ew_blocks, 256>>>(feats, g2, be2, out, n);
}

// round 16
// speedup vs baseline: 1.1379x; 1.1379x over previous
#include <cuda_runtime.h>
#include <cuda_fp16.h>
#include <cstdint>

#define C 64
#define KSZ 27
#define TM 256
#define NMAX 100000
#define EPSV 1e-5f

// 2 stages, each: A 32KB + W 8KB = 40KB
#define STAGE_BYTES 40960
#define SMEM_DYN (2 * STAGE_BYTES + 1024)

// Device scratch (no allocation allowed)
__device__ float g_y1[NMAX * C];
__device__ float g_sum1[C], g_sq1[C], g_sum2[C], g_sq2[C];
// fp16 activations, row-major [n][64] (128B rows)
__device__ __align__(16) __half g_a[NMAX * C];
// weights [conv][k][d][c] fp16, PRE-SWIZZLED for linear smem copy
__device__ __align__(16) __half g_wt[2 * KSZ * C * C];

// ---------------- helpers ----------------
static __device__ __forceinline__ uint32_t smem_u32(const void* p) {
    uint32_t a;
    asm("{ .reg .u64 t; cvta.to.shared.u64 t, %1; cvt.u32.u64 %0, t; }" : "=r"(a) : "l"(p));
    return a;
}
static __device__ __forceinline__ void cp_async16(uint32_t dst, const void* src) {
    asm volatile("cp.async.cg.shared.global [%0], [%1], 16;"
                 :: "r"(dst), "l"(__cvta_generic_to_global(src)) : "memory");
}
static __device__ __forceinline__ void cp_commit() {
    asm volatile("cp.async.commit_group;" ::: "memory");
}
static __device__ __forceinline__ void cp_wait1() {
    asm volatile("cp.async.wait_group 1;" ::: "memory");
}
static __device__ __forceinline__ void ldm4(uint32_t* r, uint32_t addr) {
    asm volatile("ldmatrix.sync.aligned.m8n8.x4.shared.b16 {%0,%1,%2,%3}, [%4];"
                 : "=r"(r[0]), "=r"(r[1]), "=r"(r[2]), "=r"(r[3]) : "r"(addr));
}
static __device__ __forceinline__ void mma_f16(float* c, const uint32_t* a, const uint32_t* b) {
    asm("mma.sync.aligned.m16n8k16.row.col.f32.f16.f16.f32 "
        "{%0,%1,%2,%3}, {%4,%5,%6,%7}, {%8,%9}, {%0,%1,%2,%3};"
        : "+f"(c[0]), "+f"(c[1]), "+f"(c[2]), "+f"(c[3])
        : "r"(a[0]), "r"(a[1]), "r"(a[2]), "r"(a[3]), "r"(b[0]), "r"(b[1]));
}

// ---------------- fused prep: zero stats + W prep + feats->fp16 ----------------
__global__ void prep_all_kernel(const float* __restrict__ W1, const float* __restrict__ W2,
                                const float* __restrict__ feats, int n) {
    int b = blockIdx.x, tid = threadIdx.x;
    if (b == 0 && tid < C) {
        g_sum1[tid] = 0.f; g_sq1[tid] = 0.f; g_sum2[tid] = 0.f; g_sq2[tid] = 0.f;
    }
    if (b < 2 * KSZ) {
        int conv = b / KSZ, k = b % KSZ;
        __half* dst = g_wt + (size_t)b * C * C;
        const float* W = ((conv == 0) ? W1 : W2) + (size_t)k * C * C;
        #pragma unroll
        for (int i = 0; i < 16; ++i) {
            int e = tid + i * 256;     // 0..4095
            int c = e >> 6, d = e & 63;
            float v = W[c * C + d];
            uint32_t sseg = (uint32_t)((c >> 3) ^ (d & 7));
            dst[(uint32_t)d * 64u + sseg * 8u + (uint32_t)(c & 7)] = __float2half_rn(v);
        }
        return;
    }
    int i = (b - 2 * KSZ) * 256 + tid;        // float4 index
    int total = n * (C / 4);
    if (i >= total) return;
    float4 v = ((const float4*)feats)[i];
    __half2 a = __floats2half2_rn(v.x, v.y);
    __half2 bb = __floats2half2_rn(v.z, v.w);
    ((uint2*)g_a)[i] = make_uint2(*(uint32_t*)&a, *(uint32_t*)&bb);
}

// y1 -> BN1(inline stats)+ReLU -> fp16 (overwrites g_a)
__global__ void prep_h1_kernel(const float* __restrict__ gamma,
                               const float* __restrict__ beta, int n) {
    __shared__ float s_sc[C], s_sh[C];
    int tid = threadIdx.x;
    if (tid < C) {
        float inv_n = 1.0f / (float)n;
        float mean = g_sum1[tid] * inv_n;
        float var = fmaxf(g_sq1[tid] * inv_n - mean * mean, 0.f);
        float sc = gamma[tid] * rsqrtf(var + EPSV);
        s_sc[tid] = sc;
        s_sh[tid] = beta[tid] - mean * sc;
    }
    __syncthreads();
    int i = blockIdx.x * blockDim.x + tid;
    int total = n * (C / 4);
    if (i >= total) return;
    int c = (i & 15) * 4;
    float4 v = ((const float4*)g_y1)[i];
    v.x = fmaxf(fmaf(v.x, s_sc[c + 0], s_sh[c + 0]), 0.f);
    v.y = fmaxf(fmaf(v.y, s_sc[c + 1], s_sh[c + 1]), 0.f);
    v.z = fmaxf(fmaf(v.z, s_sc[c + 2], s_sh[c + 2]), 0.f);
    v.w = fmaxf(fmaf(v.w, s_sc[c + 3], s_sh[c + 3]), 0.f);
    __half2 a = __floats2half2_rn(v.x, v.y);
    __half2 b = __floats2half2_rn(v.z, v.w);
    ((uint2*)g_a)[i] = make_uint2(*(uint32_t*)&a, *(uint32_t*)&b);
}

// out = relu(bn2(y2)+feats), stats2 inlined
__global__ void final_kernel(const float* __restrict__ feats,
                             const float* __restrict__ gamma,
                             const float* __restrict__ beta,
                             float* __restrict__ out, int n) {
    __shared__ float s_sc[C], s_sh[C];
    int tid = threadIdx.x;
    if (tid < C) {
        float inv_n = 1.0f / (float)n;
        float mean = g_sum2[tid] * inv_n;
        float var = fmaxf(g_sq2[tid] * inv_n - mean * mean, 0.f);
        float sc = gamma[tid] * rsqrtf(var + EPSV);
        s_sc[tid] = sc;
        s_sh[tid] = beta[tid] - mean * sc;
    }
    __syncthreads();
    int i = blockIdx.x * blockDim.x + tid;
    int total = n * (C / 4);
    if (i >= total) return;
    int c = (i & 15) * 4;
    float4 y = ((const float4*)out)[i];
    float4 f = ((const float4*)feats)[i];
    float4 r;
    r.x = fmaxf(fmaf(y.x, s_sc[c + 0], s_sh[c + 0]) + f.x, 0.f);
    r.y = fmaxf(fmaf(y.y, s_sc[c + 1], s_sh[c + 1]) + f.y, 0.f);
    r.z = fmaxf(fmaf(y.z, s_sc[c + 2], s_sh[c + 2]) + f.z, 0.f);
    r.w = fmaxf(fmaf(y.w, s_sc[c + 3], s_sh[c + 3]) + f.w, 0.f);
    ((float4*)out)[i] = r;
}

// ---------------- main conv: TM=256, warp=32x64 tile, 2-stage ring, 2 CTAs/SM ----------------
template<int PASS>
__global__ __launch_bounds__(256, 2) void conv_mma_kernel(
    const int* __restrict__ nbr, const float* __restrict__ bias,
    float* __restrict__ dout, int n)
{
    extern __shared__ char dsm[];
    __shared__ float s_sum[C], s_sq[C], s_bias[C];

    float*       yout = (PASS == 0) ? g_y1   : dout;
    float*       gsum = (PASS == 0) ? g_sum1 : g_sum2;
    float*       gsq  = (PASS == 0) ? g_sq1  : g_sq2;

    const int tid = threadIdx.x, lane = tid & 31, w = tid >> 5;
    const uint32_t base = (smem_u32(dsm) + 1023u) & ~1023u;

    if (tid < C) { s_sum[tid] = 0.f; s_sq[tid] = 0.f; s_bias[tid] = bias[tid]; }

    // ---- copy-role: 8 segs (16B) per 128B row; 8 rows per thread ----
    const int cseg = tid & 7;
    const int crow = tid >> 3;                 // 0..31, rows crow + 32i, i<8
    const long blk0 = (long)blockIdx.x * TM;

    const uint4* gw = (const uint4*)g_wt + (size_t)PASS * KSZ * 512;

    int pidx[8];
    auto load_idx = [&](int k) {
        #pragma unroll
        for (int i = 0; i < 8; ++i) {
            long r = blk0 + crow + 32 * i;
            pidx[i] = (r < (long)n) ? nbr[r * KSZ + k] : 0;
        }
    };
    auto issue_stage = [&](int k) {
        const uint32_t St = base + (uint32_t)(k & 1) * STAGE_BYTES;
        const uint32_t Wst = St + 32768u;
        #pragma unroll
        for (int i = 0; i < 8; ++i) {
            int r = crow + 32 * i;
            uint32_t dst = (uint32_t)r * 128u + (uint32_t)((cseg ^ (r & 7)) << 4);
            cp_async16(St + dst, g_a + (size_t)pidx[i] * 64 + cseg * 8);
        }
        #pragma unroll
        for (int i = 0; i < 2; ++i) {
            int jj = tid + i * 256;
            cp_async16(Wst + (uint32_t)jj * 16u, gw + (size_t)k * 512 + jj);
        }
        cp_commit();
    };

    // ---- mma-role: warp w owns rows w*32..w*32+31, ALL 64 cols ----
    const int ar0 = w * 32 + (lane & 15);
    const int ahalf = lane >> 4;
    const int ax7 = lane & 7;
    const int bd = ((lane >> 4) & 1) * 8 + (lane & 7);
    const int bkh = (lane >> 3) & 1;
    const int bx7 = bd & 7;

    float acc[2][8][4];
    #pragma unroll
    for (int tt = 0; tt < 2; ++tt)
        #pragma unroll
        for (int nt = 0; nt < 8; ++nt)
            #pragma unroll
            for (int j = 0; j < 4; ++j) acc[tt][nt][j] = 0.f;

    // ---- prologue: fill both stages ----
    load_idx(0); issue_stage(0);
    load_idx(1); issue_stage(1);
    load_idx(2);

    for (int k = 0; k < KSZ; ++k) {
        cp_wait1();
        __syncthreads();          // stage k ready

        const uint32_t St = base + (uint32_t)(k & 1) * STAGE_BYTES;
        const uint32_t Wst = St + 32768u;

        #pragma unroll
        for (int kk = 0; kk < 4; ++kk) {
            uint32_t a0[4], a1[4];
            uint32_t asel = (uint32_t)(((kk * 2 + ahalf) ^ ax7) << 4);
            ldm4(a0, St + (uint32_t)ar0 * 128u + asel);
            ldm4(a1, St + (uint32_t)(ar0 + 16) * 128u + asel);
            uint32_t bsel = (uint32_t)(((kk * 2 + bkh) ^ bx7) << 4);
            #pragma unroll
            for (int p = 0; p < 4; ++p) {
                uint32_t b[4];
                ldm4(b, Wst + (uint32_t)(p * 16 + bd) * 128u + bsel);
                mma_f16(acc[0][2 * p],     a0, b);
                mma_f16(acc[0][2 * p + 1], a0, b + 2);
                mma_f16(acc[1][2 * p],     a1, b);
                mma_f16(acc[1][2 * p + 1], a1, b + 2);
            }
        }

        if (k + 2 < KSZ) {
            __syncthreads();      // all warps done with slot k -> safe to overwrite
            issue_stage(k + 2);
            if (k + 3 < KSZ) load_idx(k + 3);
        }
    }

    // ---------------- epilogue ----------------
    const int g = lane >> 2, tig = lane & 3;

    #pragma unroll
    for (int nt = 0; nt < 8; ++nt) {
        int col = nt * 8 + tig * 2;
        float b0 = s_bias[col], b1 = s_bias[col + 1];
        float sv0 = 0.f, sv1 = 0.f, sq0 = 0.f, sq1 = 0.f;
        #pragma unroll
        for (int tt = 0; tt < 2; ++tt) {
            long row0 = blk0 + w * 32 + tt * 16 + g;
            long row1 = row0 + 8;
            bool v0 = row0 < (long)n, v1 = row1 < (long)n;
            float y00 = v0 ? acc[tt][nt][0] + b0 : 0.f;
            float y01 = v0 ? acc[tt][nt][1] + b1 : 0.f;
            float y10 = v1 ? acc[tt][nt][2] + b0 : 0.f;
            float y11 = v1 ? acc[tt][nt][3] + b1 : 0.f;
            if (v0) *(float2*)(yout + (size_t)row0 * C + col) = make_float2(y00, y01);
            if (v1) *(float2*)(yout + (size_t)row1 * C + col) = make_float2(y10, y11);
            sv0 += y00 + y10; sv1 += y01 + y11;
            sq0 += y00 * y00 + y10 * y10; sq1 += y01 * y01 + y11 * y11;
        }
        #pragma unroll
        for (int o = 16; o >= 4; o >>= 1) {
            sv0 += __shfl_xor_sync(0xffffffffu, sv0, o);
            sv1 += __shfl_xor_sync(0xffffffffu, sv1, o);
            sq0 += __shfl_xor_sync(0xffffffffu, sq0, o);
            sq1 += __shfl_xor_sync(0xffffffffu, sq1, o);
        }
        if (lane < 4) {
            atomicAdd(&s_sum[nt * 8 + lane * 2],     sv0);
            atomicAdd(&s_sum[nt * 8 + lane * 2 + 1], sv1);
            atomicAdd(&s_sq[nt * 8 + lane * 2],      sq0);
            atomicAdd(&s_sq[nt * 8 + lane * 2 + 1],  sq1);
        }
    }
    __syncthreads();
    if (tid < C) { atomicAdd(&gsum[tid], s_sum[tid]); atomicAdd(&gsq[tid], s_sq[tid]); }
}

extern "C" void kernel_launch(void* const* d_in, const int* in_sizes, int n_in,
                              void* d_out, int out_size) {
    const float* feats = (const float*)d_in[0];
    const int*   nbr   = (const int*)d_in[1];
    const float* W1    = (const float*)d_in[2];
    const float* b1    = (const float*)d_in[3];
    const float* g1    = (const float*)d_in[4];
    const float* be1   = (const float*)d_in[5];
    const float* W2    = (const float*)d_in[6];
    const float* b2    = (const float*)d_in[7];
    const float* g2    = (const float*)d_in[8];
    const float* be2   = (const float*)d_in[9];
    float* out = (float*)d_out;

    int n = in_sizes[0] / C;
    int conv_blocks = (n + TM - 1) / TM;
    int ew_blocks = (n * (C / 4) + 255) / 256;

    cudaFuncSetAttribute(conv_mma_kernel<0>, cudaFuncAttributeMaxDynamicSharedMemorySize, SMEM_DYN);
    cudaFuncSetAttribute(conv_mma_kernel<1>, cudaFuncAttributeMaxDynamicSharedMemorySize, SMEM_DYN);

    prep_all_kernel<<<2 * KSZ + ew_blocks, 256>>>(W1, W2, feats, n);
    conv_mma_kernel<0><<<conv_blocks, 256, SMEM_DYN>>>(nbr, b1, nullptr, n);
    prep_h1_kernel<<<ew_blocks, 256>>>(g1, be1, n);
    conv_mma_kernel<1><<<conv_blocks, 256, SMEM_DYN>>>(nbr, b2, out, n);
    final_kernel<<<ew_blocks, 256>>>(feats, g2, be2, out, n);
}